// round 1
// baseline (speedup 1.0000x reference)
#include <cuda_runtime.h>
#include <math.h>

#define S   256
#define SB  255     // number of scan steps (S-1)
#define B   4096
#define H   256
#define E   32
#define MM  20
#define G4  1024    // 4*H
#define KTOT 532    // MM + H + H

// ---- scratch (static device globals; allocation-free) ----
__device__ float g_T  [(size_t)SB*B*H];   // time gate per step
__device__ float g_hs1[(size_t)SB*B*H];   // shared-path hidden per step
__device__ float g_H1 [(size_t)SB*B*H];   // private hidden per step
__device__ float g_c  [(size_t)B*H];      // private cell state (carried)
__device__ float g_pre[(size_t)B*G4];     // per-step gate preactivations

__device__ __forceinline__ float sigmoidf_(float x) { return 1.f / (1.f + expf(-x)); }

// ============================================================
// K1: parallel precompute of T[t] and hs1[t] for all (t, b)
// grid (SB, B), block 256 (one thread per hidden unit j)
// ============================================================
__global__ void k_pre(const float* __restrict__ val_seq, const float* __restrict__ delta,
                      const float* __restrict__ W_d,  const float* __restrict__ b_d,
                      const float* __restrict__ W_xt, const float* __restrict__ W_dt,
                      const float* __restrict__ b_t,
                      const float* __restrict__ W_x_s, const float* __restrict__ b_s)
{
    int t = blockIdx.x;
    int b = blockIdx.y;
    int j = threadIdx.x;           // 0..255

    __shared__ float sx[MM];
    __shared__ float sdemb[E];
    if (j < MM) sx[j] = val_seq[(size_t)t*B*MM + (size_t)b*MM + j];
    if (j < E) {
        float d = delta[(size_t)t*B + b];
        sdemb[j] = tanhf(d * W_d[j] + b_d[j]);
    }
    __syncthreads();

    // time gate T = sigmoid(x@W_xt + sigmoid(demb@W_dt) + b_t)
    float tx = b_t[j];
    #pragma unroll
    for (int k = 0; k < MM; k++) tx += sx[k] * W_xt[k*H + j];
    float td = 0.f;
    #pragma unroll
    for (int e = 0; e < E; e++) td += sdemb[e] * W_dt[e*H + j];
    float T = sigmoidf_(tx + sigmoidf_(td));

    // shared path: pre_s = x@W_x_s + b_s (hs=0); cs=0 so f-gate drops out
    float is = b_s[j], os = b_s[j + 2*H], gs = b_s[j + 3*H];
    #pragma unroll
    for (int k = 0; k < MM; k++) {
        float xv = sx[k];
        const float* w = W_x_s + (size_t)k*G4;
        is += xv * w[j];
        os += xv * w[j + 2*H];
        gs += xv * w[j + 3*H];
    }
    float cns = sigmoidf_(is) * T * tanhf(gs);
    float hs1 = sigmoidf_(os) * tanhf(cns);

    size_t idx = (size_t)t*B*H + (size_t)b*H + j;
    g_T[idx]   = T;
    g_hs1[idx] = hs1;
}

// ============================================================
// K2: per-step GEMM  pre[B,1024] = [x | hs1 | h_prev] @ [W_x_p; W_s_p; W_h_p] + b_p
// 64x64 block tile, 256 threads, 4x4 microtile, K tiles of 16
// ============================================================
#define BMT 64
#define BNT 64
#define BKT 16

__global__ void k_gemm(const float* __restrict__ val_seq,
                       const float* __restrict__ W_x_p,
                       const float* __restrict__ W_h_p,
                       const float* __restrict__ W_s_p,
                       const float* __restrict__ b_p,
                       int t)
{
    __shared__ float As[BKT][BMT];   // transposed: [k][row]
    __shared__ float Bs[BKT][BNT];   // [k][col]

    int row0 = blockIdx.x * BMT;
    int col0 = blockIdx.y * BNT;
    int tid  = threadIdx.x;          // 0..255
    int tx   = tid & 15, ty = tid >> 4;

    const float* x_t   = val_seq + (size_t)t*B*MM;
    const float* hs1_t = g_hs1   + (size_t)t*B*H;
    const float* hp    = (t > 0) ? (g_H1 + (size_t)(t-1)*B*H) : nullptr;

    float acc[4][4] = {};

    for (int k0 = 0; k0 < KTOT; k0 += BKT) {
        // load A tile (BMT x BKT = 1024 elems, 4 per thread)
        #pragma unroll
        for (int i = 0; i < 4; i++) {
            int e = tid + i*256;
            int r = e >> 4;          // row within tile
            int k = e & 15;
            int kk = k0 + k;
            int row = row0 + r;
            float v = 0.f;
            if (kk < MM)            v = x_t[(size_t)row*MM + kk];
            else if (kk < MM + H)   v = hs1_t[(size_t)row*H + (kk - MM)];
            else if (kk < KTOT)     v = hp ? hp[(size_t)row*H + (kk - MM - H)] : 0.f;
            As[k][r] = v;
        }
        // load B tile (BKT x BNT)
        #pragma unroll
        for (int i = 0; i < 4; i++) {
            int e = tid + i*256;
            int k = e >> 6;          // e / 64
            int c = e & 63;
            int kk = k0 + k;
            int col = col0 + c;
            float v = 0.f;
            if (kk < MM)            v = W_x_p[(size_t)kk*G4 + col];
            else if (kk < MM + H)   v = W_s_p[(size_t)(kk - MM)*G4 + col];
            else if (kk < KTOT)     v = W_h_p[(size_t)(kk - MM - H)*G4 + col];
            Bs[k][c] = v;
        }
        __syncthreads();

        #pragma unroll
        for (int k = 0; k < BKT; k++) {
            float4 a  = *(const float4*)&As[k][ty*4];
            float4 bv = *(const float4*)&Bs[k][tx*4];
            float av[4] = {a.x, a.y, a.z, a.w};
            float bb[4] = {bv.x, bv.y, bv.z, bv.w};
            #pragma unroll
            for (int i = 0; i < 4; i++)
                #pragma unroll
                for (int jj = 0; jj < 4; jj++)
                    acc[i][jj] += av[i] * bb[jj];
        }
        __syncthreads();
    }

    #pragma unroll
    for (int i = 0; i < 4; i++) {
        int row = row0 + ty*4 + i;
        #pragma unroll
        for (int jj = 0; jj < 4; jj++) {
            int col = col0 + tx*4 + jj;
            g_pre[(size_t)row*G4 + col] = acc[i][jj] + b_p[col];
        }
    }
}

// ============================================================
// K3: per-step elementwise cell update
// ============================================================
__global__ void k_cell(int t)
{
    int idx = blockIdx.x * blockDim.x + threadIdx.x;   // over B*H
    int b = idx >> 8;
    int j = idx & 255;
    const float* pre = g_pre + (size_t)b*G4;
    float i_ = pre[j], f_ = pre[j + H], o_ = pre[j + 2*H], g_ = pre[j + 3*H];
    float T = g_T[(size_t)t*B*H + idx];
    float cprev = (t > 0) ? g_c[idx] : 0.f;
    float cn = sigmoidf_(f_) * cprev + sigmoidf_(i_) * T * tanhf(g_);
    g_c[idx] = cn;
    g_H1[(size_t)t*B*H + idx] = sigmoidf_(o_) * tanhf(cn);
}

// ============================================================
// K4: parallel output heads for all (t, b): softmax(h1@Wc+bc), h1@Wm+bm
// grid (SB, B/32), block 256
// ============================================================
#define RPB 32
__global__ void k_out(const float* __restrict__ Wc, const float* __restrict__ bc,
                      const float* __restrict__ Wm, const float* __restrict__ bm,
                      float* __restrict__ out)
{
    int t  = blockIdx.x;
    int b0 = blockIdx.y * RPB;

    __shared__ float sh[RPB][H];      // 32 KB
    __shared__ float sl[RPB][25];

    const float* h1 = g_H1 + (size_t)t*B*H + (size_t)b0*H;
    for (int e = threadIdx.x; e < RPB*H; e += blockDim.x)
        sh[e >> 8][e & 255] = h1[e];
    __syncthreads();

    for (int o = threadIdx.x; o < RPB*25; o += blockDim.x) {
        int r = o / 25, j = o % 25;
        const float* hrow = sh[r];
        float s;
        if (j < 3) {
            s = bc[j];
            #pragma unroll 8
            for (int k = 0; k < H; k++) s += hrow[k] * Wc[k*3 + j];
        } else {
            int jj = j - 3;
            s = bm[jj];
            #pragma unroll 8
            for (int k = 0; k < H; k++) s += hrow[k] * Wm[k*22 + jj];
        }
        sl[r][j] = s;
    }
    __syncthreads();

    float* out_cat = out;
    float* out_val = out + (size_t)SB*B*3;
    for (int o = threadIdx.x; o < RPB*25; o += blockDim.x) {
        int r = o / 25, j = o % 25;
        int b = b0 + r;
        if (j < 3) {
            float l0 = sl[r][0], l1 = sl[r][1], l2 = sl[r][2];
            float m  = fmaxf(l0, fmaxf(l1, l2));
            float e0 = expf(l0 - m), e1 = expf(l1 - m), e2 = expf(l2 - m);
            float inv = 1.f / (e0 + e1 + e2);
            float v = (j == 0 ? e0 : (j == 1 ? e1 : e2)) * inv;
            out_cat[(size_t)t*B*3 + (size_t)b*3 + j] = v;
        } else {
            out_val[(size_t)t*B*22 + (size_t)b*22 + (j - 3)] = sl[r][j];
        }
    }
}

// ============================================================
// launch
// ============================================================
extern "C" void kernel_launch(void* const* d_in, const int* in_sizes, int n_in,
                              void* d_out, int out_size)
{
    // metadata order (setup_inputs dict order):
    // 0 cat_seq (unused), 1 val_seq, 2 delta, 3 W_d, 4 b_d, 5 W_xt, 6 W_dt, 7 b_t,
    // 8 W_x_s, 9 W_h_s (unused), 10 b_s, 11 W_x_p, 12 W_h_p, 13 W_s_p, 14 b_p,
    // 15 Wc, 16 bc, 17 Wm, 18 bm, 19 task_name (unused)
    const float* val_seq = (const float*)d_in[1];
    const float* delta   = (const float*)d_in[2];
    const float* W_d     = (const float*)d_in[3];
    const float* b_d     = (const float*)d_in[4];
    const float* W_xt    = (const float*)d_in[5];
    const float* W_dt    = (const float*)d_in[6];
    const float* b_t     = (const float*)d_in[7];
    const float* W_x_s   = (const float*)d_in[8];
    const float* b_s     = (const float*)d_in[10];
    const float* W_x_p   = (const float*)d_in[11];
    const float* W_h_p   = (const float*)d_in[12];
    const float* W_s_p   = (const float*)d_in[13];
    const float* b_p     = (const float*)d_in[14];
    const float* Wc      = (const float*)d_in[15];
    const float* bc      = (const float*)d_in[16];
    const float* Wm      = (const float*)d_in[17];
    const float* bm      = (const float*)d_in[18];
    float* out = (float*)d_out;

    // Phase 1: parallel precompute of T and hs1 for all steps
    k_pre<<<dim3(SB, B), 256>>>(val_seq, delta, W_d, b_d, W_xt, W_dt, b_t, W_x_s, b_s);

    // Phase 2: sequential recurrence (only h @ W_h_p is truly sequential)
    for (int t = 0; t < SB; t++) {
        k_gemm<<<dim3(B/BMT, G4/BNT), 256>>>(val_seq, W_x_p, W_h_p, W_s_p, b_p, t);
        k_cell<<<(B*H)/256, 256>>>(t);
    }

    // Phase 3: parallel output heads
    k_out<<<dim3(SB, B/RPB), 256>>>(Wc, bc, Wm, bm, out);
}